// round 11
// baseline (speedup 1.0000x reference)
#include <cuda_runtime.h>
#include <cstdint>

// ---------------- problem constants ----------------
#define B_      128
#define T_IN_   240
#define T_OUT_  30
#define D_      128
#define H_      256
#define G3_     768

#define ENC_LEN 30720   // T_IN * B
#define DEC_LEN 3840    // T_OUT * B

// segmentation: 3 chains per 4-CTA cluster
#define CHAINS   3
#define CHUNK    320     // 96 enc chains * 320 = 30720 ; 12 dec chains * 320 = 3840
#define WARMUP   96
#define STEPS    (CHUNK + WARMUP)   // 416
#define NCL_ENC  32
#define NCL_DEC  4

#define NTHREADS 384     // 12 warps

// ---------------- device scratch ----------------
__device__ float g_gi_enc[(size_t)ENC_LEN * G3_];   // ~94 MB
__device__ float g_gi_dec[(size_t)DEC_LEN * G3_];   // ~12 MB

// ---------------- helpers ----------------
__device__ __forceinline__ uint32_t smem_u32(const void* p) {
    return (uint32_t)__cvta_generic_to_shared(p);
}
__device__ __forceinline__ uint32_t mapa_u32(uint32_t addr, uint32_t rank) {
    uint32_t d;
    asm("mapa.shared::cluster.u32 %0, %1, %2;" : "=r"(d) : "r"(addr), "r"(rank));
    return d;
}
__device__ __forceinline__ void cl_sync() {
    asm volatile("barrier.cluster.arrive.aligned;" ::: "memory");
    asm volatile("barrier.cluster.wait.aligned;"   ::: "memory");
}
__device__ __forceinline__ void mbar_init(uint32_t mbar, uint32_t count) {
    asm volatile("mbarrier.init.shared.b64 [%0], %1;" :: "r"(mbar), "r"(count) : "memory");
}
__device__ __forceinline__ void mbar_arrive_expect(uint32_t mbar, uint32_t bytes) {
    asm volatile("mbarrier.arrive.expect_tx.shared::cta.b64 _, [%0], %1;"
                 :: "r"(mbar), "r"(bytes) : "memory");
}
__device__ __forceinline__ void mbar_wait_parity(uint32_t mbar, uint32_t parity) {
    uint32_t done;
    asm volatile(
        "{\n\t.reg .pred p;\n\t"
        "mbarrier.try_wait.parity.acquire.cta.shared::cta.b64 p, [%1], %2;\n\t"
        "selp.b32 %0, 1, 0, p;\n\t}"
        : "=r"(done) : "r"(mbar), "r"(parity) : "memory");
    if (!done) {
        asm volatile(
            "{\n\t.reg .pred P1;\n\t"
            "WAIT_LOOP_%=:\n\t"
            "mbarrier.try_wait.parity.acquire.cta.shared::cta.b64 P1, [%0], %1, 0x989680;\n\t"
            "@P1 bra.uni WAIT_DONE_%=;\n\t"
            "bra.uni WAIT_LOOP_%=;\n\t"
            "WAIT_DONE_%=:\n\t}"
            :: "r"(mbar), "r"(parity) : "memory");
    }
}
__device__ __forceinline__ void st_async_f32(uint32_t addr, float v, uint32_t mbar) {
    asm volatile(
        "st.async.weak.shared::cluster.mbarrier::complete_tx::bytes.f32 [%0], %1, [%2];"
        :: "r"(addr), "f"(v), "r"(mbar) : "memory");
}
__device__ __forceinline__ unsigned long long ffma2(unsigned long long a,
                                                    unsigned long long b,
                                                    unsigned long long c) {
    unsigned long long r;
    asm("fma.rn.f32x2 %0, %1, %2, %3;" : "=l"(r) : "l"(a), "l"(b), "l"(c));
    return r;
}
__device__ __forceinline__ float f2lo(unsigned long long v) {
    return __uint_as_float((unsigned)(v & 0xffffffffull));
}
__device__ __forceinline__ float f2hi(unsigned long long v) {
    return __uint_as_float((unsigned)(v >> 32));
}
__device__ __forceinline__ float tanh_ap(float x) {
    float y;
    asm("tanh.approx.f32 %0, %1;" : "=f"(y) : "f"(x));
    return y;
}
__device__ __forceinline__ float sig_(float x) { return 0.5f * tanh_ap(0.5f * x) + 0.5f; }
__device__ __forceinline__ float th_(float x)  { return tanh_ap(x); }

// ============================================================
// Phase 1: GI = X @ Wih^T + bih  (unchanged — verified)
// ============================================================
__global__ __launch_bounds__(256)
void gi_gemm(const float* __restrict__ x,
             const float* __restrict__ Wih_e, const float* __restrict__ bih_e,
             const float* __restrict__ Wih_d, const float* __restrict__ bih_d)
{
    __shared__ float Xs[64][68];   // [k][pos]
    __shared__ float Ws[64][68];   // [k][gate]

    const int tileP = blockIdx.x;
    const bool enc = (tileP < (ENC_LEN / 64));
    const float* __restrict__ Wih = enc ? Wih_e : Wih_d;
    const float* __restrict__ bih = enc ? bih_e : bih_d;
    float* __restrict__ gout = enc ? g_gi_enc : g_gi_dec;
    const int p0 = (enc ? tileP : (tileP - ENC_LEN / 64)) * 64;
    const int g0 = blockIdx.y * 64;
    const int tid = threadIdx.x;
    const int tstride = enc ? 1 : 8;

    const int tx = tid & 15;
    const int ty = tid >> 4;
    float acc[4][4] = {};

    for (int kc = 0; kc < 2; ++kc) {
        #pragma unroll
        for (int i = tid; i < 64 * 64; i += 256) {
            int pos = i >> 6, k = i & 63;
            int p = p0 + pos;
            int b = p & 127, t = (p >> 7) * tstride;
            Xs[k][pos] = x[((size_t)b * T_IN_ + t) * D_ + kc * 64 + k];
        }
        #pragma unroll
        for (int i = tid; i < 64 * 64; i += 256) {
            int g = i >> 6, k = i & 63;
            Ws[k][g] = Wih[(size_t)(g0 + g) * D_ + kc * 64 + k];
        }
        __syncthreads();

        #pragma unroll 16
        for (int k = 0; k < 64; ++k) {
            float4 a = *(const float4*)&Xs[k][ty * 4];
            float4 b = *(const float4*)&Ws[k][tx * 4];
            float av[4] = {a.x, a.y, a.z, a.w};
            float bv[4] = {b.x, b.y, b.z, b.w};
            #pragma unroll
            for (int i = 0; i < 4; ++i)
                #pragma unroll
                for (int j = 0; j < 4; ++j)
                    acc[i][j] = fmaf(av[i], bv[j], acc[i][j]);
        }
        __syncthreads();
    }

    float bz[4];
    #pragma unroll
    for (int j = 0; j < 4; ++j) bz[j] = bih[g0 + tx * 4 + j];

    #pragma unroll
    for (int i = 0; i < 4; ++i) {
        int p = p0 + ty * 4 + i;
        float4 o;
        o.x = acc[i][0] + bz[0];
        o.y = acc[i][1] + bz[1];
        o.z = acc[i][2] + bz[2];
        o.w = acc[i][3] + bz[3];
        *(float4*)&gout[(size_t)p * G3_ + g0 + tx * 4] = o;
    }
}

// ============================================================
// Phase 2: segmented GRU scan — quarter-row mapping.
//   warp w: quarter q = w & 3, row-group g = w >> 2 (0..2)
//   thread (w,lane): rows r0 = g*32+lane, r1 = r0+96; k in [q*64, q*64+64)
//   => all lanes of a warp read IDENTICAL h addresses (broadcast),
//      each h LDS.128 feeds 4 FFMA2 (2 rows), LDS count halved.
// Per step: wait(mb[ph]) -> arm(mb[ph]) -> 3 matvecs ->
// __syncthreads -> gates on 192 threads (4-quarter combine) ->
// st.async all chains into ONE phase barrier. Protocol == R10.
// ============================================================
__global__ __launch_bounds__(NTHREADS, 1) __cluster_dims__(4, 1, 1)
void gru_scan(const float* __restrict__ Whh_e, const float* __restrict__ bhh_e,
              const float* __restrict__ Whh_d, const float* __restrict__ bhh_d,
              float* __restrict__ out)
{
    __shared__ __align__(16) float hbuf[2][CHAINS][256];   // [parity][chain][H]
    __shared__ float sGHp[CHAINS][4][192];                 // [chain][quarter][row]
    __shared__ float sGI[CHAINS][192];
    __shared__ float sBH[192];
    __shared__ __align__(8) unsigned long long mbars[2];   // one per parity

    const int tid  = threadIdx.x;
    const int warp = tid >> 5;
    const int lane = tid & 31;
    uint32_t rank;
    asm("mov.u32 %0, %%cluster_ctarank;" : "=r"(rank));

    const int cl   = blockIdx.x >> 2;
    const bool enc = cl < NCL_ENC;
    const int lcl  = enc ? cl : cl - NCL_ENC;
    const float* __restrict__ Whh = enc ? Whh_e : Whh_d;
    const float* __restrict__ bhh = enc ? bhh_e : bhh_d;
    const float* __restrict__ gi  = enc ? g_gi_enc : g_gi_dec;

    int base[CHAINS];
    #pragma unroll
    for (int c = 0; c < CHAINS; ++c)
        base[c] = (lcl * CHAINS + c) * CHUNK;

    const uint32_t mb_base = smem_u32(&mbars[0]);

    // ---- shared init ----
    for (int i = tid; i < 2 * CHAINS * 256; i += NTHREADS)
        ((float*)hbuf)[i] = 0.0f;
    if (tid < 192) {
        int g = tid >> 6, j = tid & 63;
        sBH[tid] = bhh[g * 256 + (int)rank * 64 + j];
    }
    if (tid == 0) {
        mbar_init(mb_base, 1);
        mbar_init(mb_base + 8, 1);
        // pre-arm mb[1]: it receives step-0 stores (3 chains x 4 ranks x 256B)
        mbar_arrive_expect(mb_base + 8, 1024 * CHAINS);
    }
    __syncthreads();
    cl_sync();   // barriers + zeroed buffers visible cluster-wide

    // ---- thread mapping: 2 rows x one k-quarter ----
    const int q  = warp & 3;            // k-quarter 0..3
    const int g  = warp >> 2;           // row-group 0..2
    const int r0 = g * 32 + lane;       // 0..95
    const int r1 = r0 + 96;             // 96..191
    const int Rg0 = (r0 >> 6) * 256 + (int)rank * 64 + (r0 & 63);
    const int Rg1 = (r1 >> 6) * 256 + (int)rank * 64 + (r1 & 63);

    // 2 x 64 weights in registers (64 packed f32x2 total)
    unsigned long long wA[32], wB[32];
    {
        const ulonglong2* w0 = (const ulonglong2*)(Whh + (size_t)Rg0 * H_ + q * 64);
        const ulonglong2* w1 = (const ulonglong2*)(Whh + (size_t)Rg1 * H_ + q * 64);
        #pragma unroll
        for (int i = 0; i < 16; ++i) {
            ulonglong2 t0 = w0[i];
            wA[2 * i] = t0.x; wA[2 * i + 1] = t0.y;
            ulonglong2 t1 = w1[i];
            wB[2 * i] = t1.x; wB[2 * i + 1] = t1.y;
        }
    }

    // peer addresses
    uint32_t peer_hb[4], peer_mb[4];
    {
        uint32_t my_hb = smem_u32(&hbuf[0][0][0]);
        #pragma unroll
        for (int r = 0; r < 4; ++r) {
            peer_hb[r] = mapa_u32(my_hb, r);
            peer_mb[r] = mapa_u32(mb_base, r);
        }
    }

    // per-chain gi pointers; q==0 threads prefetch both rows one step ahead
    const float* gp[CHAINS];
    float gin0[CHAINS], gin1[CHAINS];
    #pragma unroll
    for (int c = 0; c < CHAINS; ++c) {
        int p0 = base[c] - WARMUP; if (p0 < 0) p0 = 0;
        gp[c] = gi + (size_t)p0 * G3_;
        if (q == 0) {
            gin0[c] = __ldg(gp[c] + Rg0);
            gin1[c] = __ldg(gp[c] + Rg1);
        } else { gin0[c] = 0.0f; gin1[c] = 0.0f; }
    }

    uint32_t mph[2] = {0u, 0u};

    for (int s = 0; s < STEPS; ++s) {
        const int ph = s & 1;

        // wait for all chains' h(s) (stored at end of step s-1)
        if (s > 0) {
            mbar_wait_parity(mb_base + ph * 8, mph[ph] & 1u);
            mph[ph]++;
        }

        // arm mb[ph] for step (s+1)'s stores — AFTER the wait (unique
        // arrive of the fresh phase; R10's proven ordering).
        if (tid == 0 && s + 1 < STEPS)
            mbar_arrive_expect(mb_base + ph * 8, 1024 * CHAINS);

        // ---- 3 matvecs back-to-back ----
        #pragma unroll
        for (int c = 0; c < CHAINS; ++c) {
            float giv0 = gin0[c], giv1 = gin1[c];
            if (q == 0 && s + 1 < STEPS) {         // guarded prefetch
                if (base[c] + s + 1 > WARMUP) gp[c] += G3_;
                gin0[c] = __ldg(gp[c] + Rg0);
                gin1[c] = __ldg(gp[c] + Rg1);
            }

            const ulonglong2* h2 =
                (const ulonglong2*)(&hbuf[ph][c][0]) + q * 16;
            unsigned long long a = 0ull, b = 0ull;
            #pragma unroll
            for (int i = 0; i < 16; ++i) {
                ulonglong2 hv = h2[i];            // 1 LDS.128 -> 4 FFMA2
                a = ffma2(wA[2 * i],     hv.x, a);
                a = ffma2(wA[2 * i + 1], hv.y, a);
                b = ffma2(wB[2 * i],     hv.x, b);
                b = ffma2(wB[2 * i + 1], hv.y, b);
            }
            sGHp[c][q][r0] = f2lo(a) + f2hi(a);
            sGHp[c][q][r1] = f2lo(b) + f2hi(b);
            if (q == 0) {
                sGI[c][r0] = giv0;
                sGI[c][r1] = giv1;
            }
        }
        __syncthreads();   // all partials visible; arm ordered before stores

        // ---- gates: 192 threads = 3 chains x 64 coords ----
        if (tid < 64 * CHAINS) {
            const int c = tid >> 6;
            const int j = tid & 63;
            const int p = base[c] + s - WARMUP;

            float ghr = sGHp[c][0][j]       + sGHp[c][1][j]
                      + sGHp[c][2][j]       + sGHp[c][3][j]       + sBH[j];
            float ghz = sGHp[c][0][64 + j]  + sGHp[c][1][64 + j]
                      + sGHp[c][2][64 + j]  + sGHp[c][3][64 + j]  + sBH[64 + j];
            float ghn = sGHp[c][0][128 + j] + sGHp[c][1][128 + j]
                      + sGHp[c][2][128 + j] + sGHp[c][3][128 + j] + sBH[128 + j];
            float r_ = sig_(sGI[c][j]       + ghr);
            float z_ = sig_(sGI[c][64 + j]  + ghz);
            float n_ = th_ (sGI[c][128 + j] + r_ * ghn);
            float hold = hbuf[ph][c][(int)rank * 64 + j];
            float hn = (1.0f - z_) * n_ + z_ * hold;
            if (p < 0) hn = 0.0f;   // pre-sequence region of segment 0

            if (s + 1 < STEPS) {
                uint32_t boff = (uint32_t)((((ph ^ 1) * CHAINS + c) << 8)
                                           + (int)rank * 64 + j) * 4u;
                uint32_t moff = (uint32_t)(ph ^ 1) * 8u;
                #pragma unroll
                for (int r = 0; r < 4; ++r)
                    st_async_f32(peer_hb[r] + boff, hn, peer_mb[r] + moff);
            }

            if (s >= WARMUP) {
                if (enc) {
                    if ((p & 127) == 127) {
                        int t_out = p >> 7;
                        out[(size_t)t_out * H_ + rank * 64 + j] = hn;
                    }
                } else {
                    int b = p & 127, t = p >> 7;
                    out[(size_t)(T_IN_ * H_) +
                        ((size_t)b * T_OUT_ + t) * H_ + rank * 64 + j] = hn;
                }
            }
        }
        // no trailing barrier: next step's mbar wait provides data ordering
        // (h arrivals) and WAR protection (remote stores require our stores).
    }

    cl_sync();   // drain async traffic before cluster teardown
}

// ============================================================
// launch
// ============================================================
extern "C" void kernel_launch(void* const* d_in, const int* in_sizes, int n_in,
                              void* d_out, int out_size)
{
    const float* x     = (const float*)d_in[0];
    const float* Wih_e = (const float*)d_in[1];
    const float* Whh_e = (const float*)d_in[2];
    const float* bih_e = (const float*)d_in[3];
    const float* bhh_e = (const float*)d_in[4];
    const float* Wih_d = (const float*)d_in[5];
    const float* Whh_d = (const float*)d_in[6];
    const float* bih_d = (const float*)d_in[7];
    const float* bhh_d = (const float*)d_in[8];
    float* out = (float*)d_out;

    dim3 ggrid(ENC_LEN / 64 + DEC_LEN / 64, G3_ / 64);  // (540, 12)
    gi_gemm<<<ggrid, 256>>>(x, Wih_e, bih_e, Wih_d, bih_d);

    gru_scan<<<(NCL_ENC + NCL_DEC) * 4, NTHREADS>>>(
        Whh_e, bhh_e, Whh_d, bhh_d, out);
}